// round 2
// baseline (speedup 1.0000x reference)
#include <cuda_runtime.h>
#include <cuda_bf16.h>

// FilterLayer: y[b,c,h,w] = sum_{di,dj in 5x5} f[b, di*5+dj, h, w] * xpad[b, c, h+di, w+dj]
// x: [4,3,512,512] f32, f: [4,25,512,512] f32, out: [4,3,512,512] f32, zero padding p=2.
//
// HBM-bound problem (f stream = 105 MB dominates). Strategy:
//  - 4 pixels per thread along w -> f loads are LDG.128 (25 per thread).
//  - x tile (+2 halo each side) staged in shared memory, read back as aligned
//    LDS.128 (thread base = tx*16B -> conflict-free) + 1 scalar halo float.
//  - fully unrolled 5x5 x 3-channel FMA core.

#define TW 128   // tile width in pixels  (32 threads * 4 pixels)
#define TH 8     // tile height in pixels
#define PAD 2
#define SW (TW + 2*PAD)   // 132 floats per smem row (132*4=528B, multiple of 16)
#define SH (TH + 2*PAD)   // 12 rows
#define CH 3
#define WIN 5

__global__ __launch_bounds__(256, 4)
void FilterLayer_4664334483556_kernel(const float* __restrict__ x,
                                      const float* __restrict__ f,
                                      float* __restrict__ out,
                                      int B, int H, int W)
{
    __shared__ float sx[CH * SH * SW];   // 3*12*132*4 = 19008 bytes

    const int tx = threadIdx.x;          // 0..31
    const int ty = threadIdx.y;          // 0..7
    const int tid = ty * 32 + tx;

    const int b  = blockIdx.z;
    const int h0 = blockIdx.y * TH;
    const int w0 = blockIdx.x * TW;

    // ---- stage x tile (with zero-padded halo) into shared memory ----
    const float* xb = x + (size_t)b * CH * H * W;
    #pragma unroll 4
    for (int idx = tid; idx < CH * SH * SW; idx += 256) {
        int c   = idx / (SH * SW);
        int rem = idx - c * (SH * SW);
        int r   = rem / SW;
        int col = rem - r * SW;
        int gh = h0 + r - PAD;
        int gw = w0 + col - PAD;
        float v = 0.0f;
        if ((unsigned)gh < (unsigned)H && (unsigned)gw < (unsigned)W)
            v = xb[(size_t)c * H * W + (size_t)gh * W + gw];
        sx[idx] = v;
    }
    __syncthreads();

    const int h     = h0 + ty;        // this thread's output row
    const int wbase = tx * 4;         // first of 4 output pixels (tile-local)

    float acc[CH][4];
    #pragma unroll
    for (int c = 0; c < CH; c++)
        #pragma unroll
        for (int q = 0; q < 4; q++)
            acc[c][q] = 0.0f;

    // f plane base for this (b, h): f[((b*25 + k)*H + h)*W + w]
    const size_t f_bh = ((size_t)b * (WIN * WIN)) * H * W + (size_t)h * W + (w0 + wbase);

    #pragma unroll
    for (int di = 0; di < WIN; di++) {
        // stage the 5 filter vectors of this window row (float4 = 4 pixels)
        float4 fv[WIN];
        #pragma unroll
        for (int dj = 0; dj < WIN; dj++) {
            int k = di * WIN + dj;
            fv[dj] = *reinterpret_cast<const float4*>(f + f_bh + (size_t)k * H * W);
        }
        #pragma unroll
        for (int c = 0; c < CH; c++) {
            // x row segment: smem cols [wbase .. wbase+8] of row (ty+di), channel c.
            // wbase*4 bytes = tx*16 -> 16B aligned; row stride 528B (16B multiple).
            const float* row = &sx[c * (SH * SW) + (ty + di) * SW + wbase];
            float xr[9];
            float4 a = *reinterpret_cast<const float4*>(row);
            float4 bq = *reinterpret_cast<const float4*>(row + 4);
            xr[0] = a.x;  xr[1] = a.y;  xr[2] = a.z;  xr[3] = a.w;
            xr[4] = bq.x; xr[5] = bq.y; xr[6] = bq.z; xr[7] = bq.w;
            xr[8] = row[8];
            #pragma unroll
            for (int dj = 0; dj < WIN; dj++) {
                acc[c][0] = fmaf(fv[dj].x, xr[dj + 0], acc[c][0]);
                acc[c][1] = fmaf(fv[dj].y, xr[dj + 1], acc[c][1]);
                acc[c][2] = fmaf(fv[dj].z, xr[dj + 2], acc[c][2]);
                acc[c][3] = fmaf(fv[dj].w, xr[dj + 3], acc[c][3]);
            }
        }
    }

    // ---- store: 3 channels x float4, 16B aligned ----
    float* ob = out + (size_t)b * CH * H * W + (size_t)h * W + (w0 + wbase);
    #pragma unroll
    for (int c = 0; c < CH; c++) {
        float4 v = make_float4(acc[c][0], acc[c][1], acc[c][2], acc[c][3]);
        *reinterpret_cast<float4*>(ob + (size_t)c * H * W) = v;
    }
}

extern "C" void kernel_launch(void* const* d_in, const int* in_sizes, int n_in,
                              void* d_out, int out_size)
{
    const float* x = (const float*)d_in[0];
    const float* f = (const float*)d_in[1];
    float* out = (float*)d_out;

    const int B = 4, H = 512, W = 512;

    dim3 block(32, 8, 1);
    dim3 grid(W / TW, H / TH, B);   // (4, 64, 4) = 1024 blocks
    FilterLayer_4664334483556_kernel<<<grid, block>>>(x, f, out, B, H, W);
}

// round 3
// speedup vs baseline: 1.3661x; 1.3661x over previous
#include <cuda_runtime.h>
#include <cuda_bf16.h>

// FilterLayer: y[b,c,h,w] = sum_{di,dj in 5x5} f[b, di*5+dj, h, w] * xpad[b, c, h+di, w+dj]
// x: [4,3,512,512] f32, f: [4,25,512,512] f32, out: [4,3,512,512] f32, zero pad p=2.
//
// R2 design: no shared memory, no barrier.
//  - f (105 MB dominant stream, zero reuse): __ldcg float4 -> L2 path, keeps L1 clean.
//  - x (12.6 MB, 25x reuse): default-cached float4 LDG; per-block footprint ~19KB
//    lives in L1, whole tensor lives in L2 -> x DRAM traffic stays ~12.6 MB.
//  - 4 pixels/thread: taps need cols [wb-2, wb+5] = 8 floats = 3 aligned float4
//    (v0 covers wb-4..wb-1, v1 wb..wb+3, v2 wb+4..wb+7); edge vectors are
//    all-or-nothing OOB because wb is a multiple of 4 and pad = 2.
//  - per di: 5 f LDG.128 + 9 x LDG.128 issued back-to-back -> high MLP.

#define WIN 5
#define CH 3

__global__ __launch_bounds__(256, 4)
void FilterLayer_4664334483556_kernel(const float* __restrict__ x,
                                      const float* __restrict__ f,
                                      float* __restrict__ out)
{
    const int H = 512, W = 512;
    const int tx = threadIdx.x;              // 0..31
    const int ty = threadIdx.y;              // 0..7
    const int b  = blockIdx.z;
    const int h  = blockIdx.y * 8 + ty;      // output row
    const int wb = blockIdx.x * 128 + tx * 4;// first of 4 output cols

    const bool leftOK  = (wb >= 4);          // v0 vector fully in-bounds
    const bool rightOK = (wb <= W - 8);      // v2 vector fully in-bounds

    float acc[CH][4];
    #pragma unroll
    for (int c = 0; c < CH; c++)
        #pragma unroll
        for (int q = 0; q < 4; q++)
            acc[c][q] = 0.0f;

    const size_t HW = (size_t)H * W;
    const float* fbase = f + ((size_t)b * (WIN * WIN)) * HW + (size_t)h * W + wb;
    const float* xbase = x + (size_t)b * CH * HW + wb;

    #pragma unroll
    for (int di = 0; di < WIN; di++) {
        const int gh = h + di - 2;
        const bool rv = ((unsigned)gh < (unsigned)H);

        // ---- filter row: 5 x LDG.128 via L2 (streaming, keep L1 for x) ----
        float4 fv[WIN];
        #pragma unroll
        for (int dj = 0; dj < WIN; dj++)
            fv[dj] = __ldcg(reinterpret_cast<const float4*>(
                         fbase + (size_t)(di * WIN + dj) * HW));

        #pragma unroll
        for (int c = 0; c < CH; c++) {
            const float* row = xbase + ((size_t)c * H + gh) * W;

            float4 v0 = make_float4(0.f, 0.f, 0.f, 0.f);
            float4 v1 = make_float4(0.f, 0.f, 0.f, 0.f);
            float4 v2 = make_float4(0.f, 0.f, 0.f, 0.f);
            if (rv) {
                if (leftOK)  v0 = __ldca(reinterpret_cast<const float4*>(row - 4));
                             v1 = __ldca(reinterpret_cast<const float4*>(row));
                if (rightOK) v2 = __ldca(reinterpret_cast<const float4*>(row + 4));
            }

            // xr[i] = x[col wb-2+i], i in [0,8)
            float xr[8];
            xr[0] = v0.z; xr[1] = v0.w;
            xr[2] = v1.x; xr[3] = v1.y; xr[4] = v1.z; xr[5] = v1.w;
            xr[6] = v2.x; xr[7] = v2.y;

            #pragma unroll
            for (int dj = 0; dj < WIN; dj++) {
                acc[c][0] = fmaf(fv[dj].x, xr[dj + 0], acc[c][0]);
                acc[c][1] = fmaf(fv[dj].y, xr[dj + 1], acc[c][1]);
                acc[c][2] = fmaf(fv[dj].z, xr[dj + 2], acc[c][2]);
                acc[c][3] = fmaf(fv[dj].w, xr[dj + 3], acc[c][3]);
            }
        }
    }

    float* ob = out + (size_t)b * CH * HW + (size_t)h * W + wb;
    #pragma unroll
    for (int c = 0; c < CH; c++) {
        float4 v = make_float4(acc[c][0], acc[c][1], acc[c][2], acc[c][3]);
        *reinterpret_cast<float4*>(ob + c * HW) = v;
    }
}

extern "C" void kernel_launch(void* const* d_in, const int* in_sizes, int n_in,
                              void* d_out, int out_size)
{
    const float* x = (const float*)d_in[0];
    const float* f = (const float*)d_in[1];
    float* out = (float*)d_out;

    dim3 block(32, 8, 1);
    dim3 grid(4, 64, 4);   // (512/128, 512/8, B) = 1024 blocks
    FilterLayer_4664334483556_kernel<<<grid, block>>>(x, f, out);
}

// round 4
// speedup vs baseline: 1.4005x; 1.0252x over previous
#include <cuda_runtime.h>
#include <cuda_bf16.h>

// FilterLayer: y[b,c,h,w] = sum_{di,dj in 5x5} f[b, di*5+dj, h, w] * xpad[b, c, h+di, w+dj]
// x: [4,3,512,512] f32, f: [4,25,512,512] f32, out: [4,3,512,512] f32, zero pad p=2.
//
// R3: latency-hiding pass.
//  - f stream software-pipelined: double-buffered fv[2][5]; next di's 5 LDG.128
//    issued before current di's FMAs -> ~10 f4 loads in flight per thread.
//  - __launch_bounds__(128, 6): reg cap 85 so the double buffer doesn't spill.
//  - 128-thread blocks / 2048 blocks: finer wave granularity, smaller tail.
//  - f via __ldcg (L2 path, no L1 pollution); x via __ldca (L1-resident, 25x reuse).

#define WIN 5
#define CH 3

__global__ __launch_bounds__(128, 6)
void FilterLayer_4664334483556_kernel(const float* __restrict__ x,
                                      const float* __restrict__ f,
                                      float* __restrict__ out)
{
    const int H = 512, W = 512;
    const int tx = threadIdx.x;               // 0..31
    const int ty = threadIdx.y;               // 0..3
    const int b  = blockIdx.z;
    const int h  = blockIdx.y * 4 + ty;       // output row
    const int wb = blockIdx.x * 128 + tx * 4; // first of 4 output cols

    const bool leftOK  = (wb >= 4);
    const bool rightOK = (wb <= W - 8);

    float acc[CH][4];
    #pragma unroll
    for (int c = 0; c < CH; c++)
        #pragma unroll
        for (int q = 0; q < 4; q++)
            acc[c][q] = 0.0f;

    const size_t HW = (size_t)H * W;
    const float* fbase = f + ((size_t)b * (WIN * WIN)) * HW + (size_t)h * W + wb;
    const float* xbase = x + (size_t)b * CH * HW + wb;

    // ---- prologue: issue f loads for di = 0 ----
    float4 fv[2][WIN];
    #pragma unroll
    for (int dj = 0; dj < WIN; dj++)
        fv[0][dj] = __ldcg(reinterpret_cast<const float4*>(fbase + (size_t)dj * HW));

    #pragma unroll
    for (int di = 0; di < WIN; di++) {
        const int cur = di & 1;
        // ---- prefetch f for di+1 before consuming di ----
        if (di < WIN - 1) {
            #pragma unroll
            for (int dj = 0; dj < WIN; dj++)
                fv[cur ^ 1][dj] = __ldcg(reinterpret_cast<const float4*>(
                    fbase + (size_t)((di + 1) * WIN + dj) * HW));
        }

        const int gh = h + di - 2;
        const bool rv = ((unsigned)gh < (unsigned)H);

        #pragma unroll
        for (int c = 0; c < CH; c++) {
            const float* row = xbase + ((size_t)c * H + gh) * W;

            float4 v0 = make_float4(0.f, 0.f, 0.f, 0.f);
            float4 v1 = make_float4(0.f, 0.f, 0.f, 0.f);
            float4 v2 = make_float4(0.f, 0.f, 0.f, 0.f);
            if (rv) {
                if (leftOK)  v0 = __ldca(reinterpret_cast<const float4*>(row - 4));
                             v1 = __ldca(reinterpret_cast<const float4*>(row));
                if (rightOK) v2 = __ldca(reinterpret_cast<const float4*>(row + 4));
            }

            float xr[8];
            xr[0] = v0.z; xr[1] = v0.w;
            xr[2] = v1.x; xr[3] = v1.y; xr[4] = v1.z; xr[5] = v1.w;
            xr[6] = v2.x; xr[7] = v2.y;

            #pragma unroll
            for (int dj = 0; dj < WIN; dj++) {
                acc[c][0] = fmaf(fv[cur][dj].x, xr[dj + 0], acc[c][0]);
                acc[c][1] = fmaf(fv[cur][dj].y, xr[dj + 1], acc[c][1]);
                acc[c][2] = fmaf(fv[cur][dj].z, xr[dj + 2], acc[c][2]);
                acc[c][3] = fmaf(fv[cur][dj].w, xr[dj + 3], acc[c][3]);
            }
        }
    }

    float* ob = out + (size_t)b * CH * HW + (size_t)h * W + wb;
    #pragma unroll
    for (int c = 0; c < CH; c++) {
        float4 v = make_float4(acc[c][0], acc[c][1], acc[c][2], acc[c][3]);
        *reinterpret_cast<float4*>(ob + c * HW) = v;
    }
}

extern "C" void kernel_launch(void* const* d_in, const int* in_sizes, int n_in,
                              void* d_out, int out_size)
{
    const float* x = (const float*)d_in[0];
    const float* f = (const float*)d_in[1];
    float* out = (float*)d_out;

    dim3 block(32, 4, 1);
    dim3 grid(4, 128, 4);   // (512/128, 512/4, B) = 2048 blocks
    FilterLayer_4664334483556_kernel<<<grid, block>>>(x, f, out);
}